// round 1
// baseline (speedup 1.0000x reference)
#include <cuda_runtime.h>
#include <cuda_bf16.h>
#include <mma.h>

using namespace nvcuda;

// Problem constants
constexpr int B = 2, S = 2048, D = 1024, H = 16, HD = 64;
constexpr size_t NEL = (size_t)B * S * D;   // 4194304 (one [B,S,D] tensor)
constexpr size_t WEL = (size_t)D * D;       // 1048576 (one weight matrix)

// ---------------- scratch arena (static __device__, no allocs) ----------------
constexpr size_t OFF_IN_HI  = 0;
constexpr size_t OFF_IN_LO  = OFF_IN_HI  + 3 * NEL * 2;
constexpr size_t OFF_W_HI   = OFF_IN_LO  + 3 * NEL * 2;
constexpr size_t OFF_W_LO   = OFF_W_HI   + 4 * WEL * 2;
constexpr size_t OFF_QKV_F  = OFF_W_LO   + 4 * WEL * 2;   // q,k,v fp32 proj results
constexpr size_t OFF_QKV_HI = OFF_QKV_F  + 3 * NEL * 4;
constexpr size_t OFF_QKV_LO = OFF_QKV_HI + 3 * NEL * 2;
constexpr size_t OFF_XH     = OFF_QKV_LO + 3 * NEL * 2;   // attn@V result fp32
constexpr size_t OFF_XH_HI  = OFF_XH     + NEL * 4;
constexpr size_t OFF_XH_LO  = OFF_XH_HI  + NEL * 2;
constexpr size_t ARENA_BYTES = OFF_XH_LO + NEL * 2;

__device__ __align__(256) unsigned char g_arena[ARENA_BYTES];

// ---------------- split fp32 -> bf16 hi/lo (optionally +bias) ----------------
__global__ void split_kernel(const float* __restrict__ src_ext, size_t src_off,
                             size_t hi_off, size_t lo_off,
                             const float* __restrict__ bias, int n)
{
    int i = blockIdx.x * blockDim.x + threadIdx.x;
    if (i >= n) return;
    const float* src = src_ext ? src_ext : (const float*)(g_arena + src_off);
    __nv_bfloat16* hi = (__nv_bfloat16*)(g_arena + hi_off);
    __nv_bfloat16* lo = (__nv_bfloat16*)(g_arena + lo_off);
    float x = src[i];
    if (bias) x += bias[i & (D - 1)];
    __nv_bfloat16 h = __float2bfloat16(x);
    hi[i] = h;
    lo[i] = __float2bfloat16(x - __bfloat162float(h));
}

// ---------------- GEMM: C[4096,1024] = A[4096,1024] @ W[1024,1024]^T ----------
// split-bf16 3-product emulation of fp32, wmma 16x16x16, block tile 128x128
__global__ __launch_bounds__(256) void gemm_kernel(
    size_t ahi_off, size_t alo_off, size_t whi_off, size_t wlo_off,
    float* __restrict__ cext, size_t c_off)
{
    const __nv_bfloat16* Ahi = (const __nv_bfloat16*)(g_arena + ahi_off);
    const __nv_bfloat16* Alo = (const __nv_bfloat16*)(g_arena + alo_off);
    const __nv_bfloat16* Whi = (const __nv_bfloat16*)(g_arena + whi_off);
    const __nv_bfloat16* Wlo = (const __nv_bfloat16*)(g_arena + wlo_off);
    float* C = cext ? cext : (float*)(g_arena + c_off);

    __shared__ __align__(16) __nv_bfloat16 As_hi[128][40], As_lo[128][40];
    __shared__ __align__(16) __nv_bfloat16 Bs_hi[128][40], Bs_lo[128][40];

    int m0 = blockIdx.y * 128, n0 = blockIdx.x * 128;
    int tid = threadIdx.x, wid = tid >> 5;
    int wm = wid & 1, wn = wid >> 1;   // warp tile 64(m) x 32(n)

    wmma::fragment<wmma::accumulator, 16, 16, 16, float> acc[4][2];
#pragma unroll
    for (int i = 0; i < 4; i++)
#pragma unroll
        for (int j = 0; j < 2; j++) wmma::fill_fragment(acc[i][j], 0.0f);

    for (int k0 = 0; k0 < D; k0 += 32) {
        for (int v = tid; v < 1024; v += 256) {           // 128x32 / vec4
            int r = v >> 3, c4 = (v & 7) * 4;
            *(uint2*)&As_hi[r][c4] = *(const uint2*)(Ahi + (size_t)(m0 + r) * D + k0 + c4);
            *(uint2*)&As_lo[r][c4] = *(const uint2*)(Alo + (size_t)(m0 + r) * D + k0 + c4);
            *(uint2*)&Bs_hi[r][c4] = *(const uint2*)(Whi + (size_t)(n0 + r) * D + k0 + c4);
            *(uint2*)&Bs_lo[r][c4] = *(const uint2*)(Wlo + (size_t)(n0 + r) * D + k0 + c4);
        }
        __syncthreads();
#pragma unroll
        for (int kk = 0; kk < 32; kk += 16) {
            wmma::fragment<wmma::matrix_a, 16, 16, 16, __nv_bfloat16, wmma::row_major> ah[4], al[4];
            wmma::fragment<wmma::matrix_b, 16, 16, 16, __nv_bfloat16, wmma::col_major> bh[2], bl[2];
#pragma unroll
            for (int i = 0; i < 4; i++) {
                wmma::load_matrix_sync(ah[i], &As_hi[wm * 64 + i * 16][kk], 40);
                wmma::load_matrix_sync(al[i], &As_lo[wm * 64 + i * 16][kk], 40);
            }
#pragma unroll
            for (int j = 0; j < 2; j++) {
                wmma::load_matrix_sync(bh[j], &Bs_hi[wn * 32 + j * 16][kk], 40);
                wmma::load_matrix_sync(bl[j], &Bs_lo[wn * 32 + j * 16][kk], 40);
            }
#pragma unroll
            for (int i = 0; i < 4; i++)
#pragma unroll
                for (int j = 0; j < 2; j++) {
                    wmma::mma_sync(acc[i][j], ah[i], bh[j], acc[i][j]);
                    wmma::mma_sync(acc[i][j], ah[i], bl[j], acc[i][j]);
                    wmma::mma_sync(acc[i][j], al[i], bh[j], acc[i][j]);
                }
        }
        __syncthreads();
    }
#pragma unroll
    for (int i = 0; i < 4; i++)
#pragma unroll
        for (int j = 0; j < 2; j++) {
            float* p = C + (size_t)(m0 + wm * 64 + i * 16) * D + n0 + wn * 32 + j * 16;
            wmma::store_matrix_sync(p, acc[i][j], D, wmma::mem_row_major);
        }
}

// ---------------- scores: attn_raw[bh, q, k] = (q . k) / 8 --------------------
__global__ __launch_bounds__(256) void scores_kernel(
    size_t qhi_off, size_t qlo_off, size_t khi_off, size_t klo_off,
    float* __restrict__ attn)
{
    const __nv_bfloat16* Qhi = (const __nv_bfloat16*)(g_arena + qhi_off);
    const __nv_bfloat16* Qlo = (const __nv_bfloat16*)(g_arena + qlo_off);
    const __nv_bfloat16* Khi = (const __nv_bfloat16*)(g_arena + khi_off);
    const __nv_bfloat16* Klo = (const __nv_bfloat16*)(g_arena + klo_off);

    int bh = blockIdx.y;
    int b = bh / H, h = bh % H;
    int q0 = blockIdx.x * 64;
    int tid = threadIdx.x, wid = tid >> 5;
    int wm = wid & 1, wn = wid >> 1;   // warp tile 32(m) x 16(n) in 64x64 block tile

    __shared__ __align__(16) __nv_bfloat16 Qh[64][72], Ql[64][72];
    __shared__ __align__(16) __nv_bfloat16 Kh[64][72], Kl[64][72];

    // load Q tile 64x64 once
    size_t qbase = ((size_t)b * S + q0) * D + h * HD;
    for (int v = tid; v < 1024; v += 256) {
        int r = v >> 4, c4 = (v & 15) * 4;
        *(uint2*)&Qh[r][c4] = *(const uint2*)(Qhi + qbase + (size_t)r * D + c4);
        *(uint2*)&Ql[r][c4] = *(const uint2*)(Qlo + qbase + (size_t)r * D + c4);
    }
    __syncthreads();

    for (int n0 = 0; n0 < S; n0 += 64) {
        size_t kbase = ((size_t)b * S + n0) * D + h * HD;
        for (int v = tid; v < 1024; v += 256) {
            int r = v >> 4, c4 = (v & 15) * 4;
            *(uint2*)&Kh[r][c4] = *(const uint2*)(Khi + kbase + (size_t)r * D + c4);
            *(uint2*)&Kl[r][c4] = *(const uint2*)(Klo + kbase + (size_t)r * D + c4);
        }
        __syncthreads();

        wmma::fragment<wmma::accumulator, 16, 16, 16, float> acc[2];
        wmma::fill_fragment(acc[0], 0.0f);
        wmma::fill_fragment(acc[1], 0.0f);
#pragma unroll
        for (int kk = 0; kk < HD; kk += 16) {
            wmma::fragment<wmma::matrix_a, 16, 16, 16, __nv_bfloat16, wmma::row_major> ah[2], al[2];
            wmma::fragment<wmma::matrix_b, 16, 16, 16, __nv_bfloat16, wmma::col_major> bh_, bl_;
#pragma unroll
            for (int i = 0; i < 2; i++) {
                wmma::load_matrix_sync(ah[i], &Qh[wm * 32 + i * 16][kk], 72);
                wmma::load_matrix_sync(al[i], &Ql[wm * 32 + i * 16][kk], 72);
            }
            wmma::load_matrix_sync(bh_, &Kh[wn * 16][kk], 72);
            wmma::load_matrix_sync(bl_, &Kl[wn * 16][kk], 72);
#pragma unroll
            for (int i = 0; i < 2; i++) {
                wmma::mma_sync(acc[i], ah[i], bh_, acc[i]);
                wmma::mma_sync(acc[i], ah[i], bl_, acc[i]);
                wmma::mma_sync(acc[i], al[i], bh_, acc[i]);
            }
        }
#pragma unroll
        for (int i = 0; i < 2; i++) {
            for (int t = 0; t < acc[i].num_elements; t++) acc[i].x[t] *= 0.125f;
            float* p = attn + ((size_t)bh * S + q0 + wm * 32 + i * 16) * S + n0 + wn * 16;
            wmma::store_matrix_sync(p, acc[i], S, wmma::mem_row_major);
        }
        __syncthreads();
    }
}

// ---------------- softmax (with mask) over last dim, in place ----------------
__global__ __launch_bounds__(256) void softmax_kernel(float* __restrict__ attn,
                                                      const int* __restrict__ mask)
{
    size_t row = blockIdx.x;                 // B*H*S rows
    int b = (int)(row / ((size_t)H * S));
    float* p = attn + row * S;
    const int* mrow = mask + (size_t)b * S;
    int tid = threadIdx.x;

    float v[8];
    float mx = -3.0e38f;
#pragma unroll
    for (int i = 0; i < 8; i++) {
        int c = tid + i * 256;
        float s = p[c];
        if (mrow[c] == 0) s = -1e9f;
        v[i] = s;
        mx = fmaxf(mx, s);
    }
    __shared__ float red[8];
#pragma unroll
    for (int o = 16; o; o >>= 1) mx = fmaxf(mx, __shfl_xor_sync(0xffffffffu, mx, o));
    if ((tid & 31) == 0) red[tid >> 5] = mx;
    __syncthreads();
    mx = red[0];
#pragma unroll
    for (int i = 1; i < 8; i++) mx = fmaxf(mx, red[i]);

    float sum = 0.0f;
#pragma unroll
    for (int i = 0; i < 8; i++) { v[i] = expf(v[i] - mx); sum += v[i]; }
#pragma unroll
    for (int o = 16; o; o >>= 1) sum += __shfl_xor_sync(0xffffffffu, sum, o);
    __syncthreads();
    if ((tid & 31) == 0) red[tid >> 5] = sum;
    __syncthreads();
    sum = 0.0f;
#pragma unroll
    for (int i = 0; i < 8; i++) sum += red[i];
    float inv = 1.0f / sum;
#pragma unroll
    for (int i = 0; i < 8; i++) p[tid + i * 256] = v[i] * inv;
}

// ---------------- x_heads[b,s,h*64+d] = sum_k attn[bh,s,k] * v[b,k,h*64+d] ----
__global__ __launch_bounds__(256) void av_kernel(
    const float* __restrict__ attn, size_t vhi_off, size_t vlo_off, size_t xh_off)
{
    const __nv_bfloat16* Vhi = (const __nv_bfloat16*)(g_arena + vhi_off);
    const __nv_bfloat16* Vlo = (const __nv_bfloat16*)(g_arena + vlo_off);
    float* XH = (float*)(g_arena + xh_off);

    int bh = blockIdx.y;
    int b = bh / H, h = bh % H;
    int q0 = blockIdx.x * 128;
    int tid = threadIdx.x, wid = tid >> 5;
    int wm = wid & 3, wn = wid >> 2;   // warp tile 32(m) x 32(n) in 128x64

    __shared__ __align__(16) __nv_bfloat16 As_hi[128][40], As_lo[128][40];
    __shared__ __align__(16) __nv_bfloat16 Vh[32][72], Vl[32][72];

    wmma::fragment<wmma::accumulator, 16, 16, 16, float> acc[2][2];
#pragma unroll
    for (int i = 0; i < 2; i++)
#pragma unroll
        for (int j = 0; j < 2; j++) wmma::fill_fragment(acc[i][j], 0.0f);

    for (int k0 = 0; k0 < S; k0 += 32) {
        // attn tile 128x32 fp32 -> split bf16 in smem
        for (int v = tid; v < 1024; v += 256) {
            int r = v >> 3, c4 = (v & 7) * 4;
            float4 f = *(const float4*)(attn + ((size_t)bh * S + q0 + r) * S + k0 + c4);
            float fs[4] = {f.x, f.y, f.z, f.w};
#pragma unroll
            for (int u = 0; u < 4; u++) {
                __nv_bfloat16 hh = __float2bfloat16(fs[u]);
                As_hi[r][c4 + u] = hh;
                As_lo[r][c4 + u] = __float2bfloat16(fs[u] - __bfloat162float(hh));
            }
        }
        // V tile 32x64
        size_t vbase = ((size_t)b * S + k0) * D + h * HD;
        for (int v = tid; v < 512; v += 256) {
            int r = v >> 4, c4 = (v & 15) * 4;
            *(uint2*)&Vh[r][c4] = *(const uint2*)(Vhi + vbase + (size_t)r * D + c4);
            *(uint2*)&Vl[r][c4] = *(const uint2*)(Vlo + vbase + (size_t)r * D + c4);
        }
        __syncthreads();
#pragma unroll
        for (int kk = 0; kk < 32; kk += 16) {
            wmma::fragment<wmma::matrix_a, 16, 16, 16, __nv_bfloat16, wmma::row_major> ah[2], al[2];
            wmma::fragment<wmma::matrix_b, 16, 16, 16, __nv_bfloat16, wmma::row_major> bh_[2], bl_[2];
#pragma unroll
            for (int i = 0; i < 2; i++) {
                wmma::load_matrix_sync(ah[i], &As_hi[wm * 32 + i * 16][kk], 40);
                wmma::load_matrix_sync(al[i], &As_lo[wm * 32 + i * 16][kk], 40);
            }
#pragma unroll
            for (int j = 0; j < 2; j++) {
                wmma::load_matrix_sync(bh_[j], &Vh[kk][wn * 32 + j * 16], 72);
                wmma::load_matrix_sync(bl_[j], &Vl[kk][wn * 32 + j * 16], 72);
            }
#pragma unroll
            for (int i = 0; i < 2; i++)
#pragma unroll
                for (int j = 0; j < 2; j++) {
                    wmma::mma_sync(acc[i][j], ah[i], bh_[j], acc[i][j]);
                    wmma::mma_sync(acc[i][j], ah[i], bl_[j], acc[i][j]);
                    wmma::mma_sync(acc[i][j], al[i], bh_[j], acc[i][j]);
                }
        }
        __syncthreads();
    }
#pragma unroll
    for (int i = 0; i < 2; i++)
#pragma unroll
        for (int j = 0; j < 2; j++) {
            float* p = XH + ((size_t)b * S + q0 + wm * 32 + i * 16) * D + h * HD + wn * 32 + j * 16;
            wmma::store_matrix_sync(p, acc[i][j], D, wmma::mem_row_major);
        }
}

// ---------------- bias add on final output ----------------
__global__ void bias_add_kernel(float* __restrict__ out, const float* __restrict__ bias, int n)
{
    int i = blockIdx.x * blockDim.x + threadIdx.x;
    if (i < n) out[i] += bias[i & (D - 1)];
}

// ---------------- launch ----------------
extern "C" void kernel_launch(void* const* d_in, const int* in_sizes, int n_in,
                              void* d_out, int out_size)
{
    const float* query = (const float*)d_in[0];
    const float* key   = (const float*)d_in[1];
    const float* value = (const float*)d_in[2];
    const int*   mask  = (const int*)d_in[3];
    const float* Wq    = (const float*)d_in[4];
    const float* bq    = (const float*)d_in[5];
    const float* Wk    = (const float*)d_in[6];
    const float* bk    = (const float*)d_in[7];
    const float* Wv    = (const float*)d_in[8];
    const float* bv    = (const float*)d_in[9];
    const float* Wo    = (const float*)d_in[10];
    const float* bo    = (const float*)d_in[11];

    float* out_x = (float*)d_out;            // [B,S,D]
    float* attn  = out_x + NEL;              // [B,H,S,S]

    int nblk = (int)(NEL / 256);             // 16384
    int wblk = (int)(WEL / 256);             // 4096

    // split inputs + weights to bf16 hi/lo
    split_kernel<<<nblk, 256>>>(query, 0, OFF_IN_HI + 0 * NEL * 2, OFF_IN_LO + 0 * NEL * 2, nullptr, (int)NEL);
    split_kernel<<<nblk, 256>>>(key,   0, OFF_IN_HI + 1 * NEL * 2, OFF_IN_LO + 1 * NEL * 2, nullptr, (int)NEL);
    split_kernel<<<nblk, 256>>>(value, 0, OFF_IN_HI + 2 * NEL * 2, OFF_IN_LO + 2 * NEL * 2, nullptr, (int)NEL);
    split_kernel<<<wblk, 256>>>(Wq, 0, OFF_W_HI + 0 * WEL * 2, OFF_W_LO + 0 * WEL * 2, nullptr, (int)WEL);
    split_kernel<<<wblk, 256>>>(Wk, 0, OFF_W_HI + 1 * WEL * 2, OFF_W_LO + 1 * WEL * 2, nullptr, (int)WEL);
    split_kernel<<<wblk, 256>>>(Wv, 0, OFF_W_HI + 2 * WEL * 2, OFF_W_LO + 2 * WEL * 2, nullptr, (int)WEL);
    split_kernel<<<wblk, 256>>>(Wo, 0, OFF_W_HI + 3 * WEL * 2, OFF_W_LO + 3 * WEL * 2, nullptr, (int)WEL);

    // QKV projections (no bias yet)
    dim3 ggrid(8, 32);
    gemm_kernel<<<ggrid, 256>>>(OFF_IN_HI + 0 * NEL * 2, OFF_IN_LO + 0 * NEL * 2,
                                OFF_W_HI + 0 * WEL * 2, OFF_W_LO + 0 * WEL * 2,
                                nullptr, OFF_QKV_F + 0 * NEL * 4);
    gemm_kernel<<<ggrid, 256>>>(OFF_IN_HI + 1 * NEL * 2, OFF_IN_LO + 1 * NEL * 2,
                                OFF_W_HI + 1 * WEL * 2, OFF_W_LO + 1 * WEL * 2,
                                nullptr, OFF_QKV_F + 1 * NEL * 4);
    gemm_kernel<<<ggrid, 256>>>(OFF_IN_HI + 2 * NEL * 2, OFF_IN_LO + 2 * NEL * 2,
                                OFF_W_HI + 2 * WEL * 2, OFF_W_LO + 2 * WEL * 2,
                                nullptr, OFF_QKV_F + 2 * NEL * 4);

    // bias add + split q,k,v to bf16 hi/lo
    split_kernel<<<nblk, 256>>>(nullptr, OFF_QKV_F + 0 * NEL * 4,
                                OFF_QKV_HI + 0 * NEL * 2, OFF_QKV_LO + 0 * NEL * 2, bq, (int)NEL);
    split_kernel<<<nblk, 256>>>(nullptr, OFF_QKV_F + 1 * NEL * 4,
                                OFF_QKV_HI + 1 * NEL * 2, OFF_QKV_LO + 1 * NEL * 2, bk, (int)NEL);
    split_kernel<<<nblk, 256>>>(nullptr, OFF_QKV_F + 2 * NEL * 4,
                                OFF_QKV_HI + 2 * NEL * 2, OFF_QKV_LO + 2 * NEL * 2, bv, (int)NEL);

    // raw scores -> attn region
    scores_kernel<<<dim3(S / 64, B * H), 256>>>(OFF_QKV_HI + 0 * NEL * 2, OFF_QKV_LO + 0 * NEL * 2,
                                                OFF_QKV_HI + 1 * NEL * 2, OFF_QKV_LO + 1 * NEL * 2,
                                                attn);
    // masked softmax in place
    softmax_kernel<<<B * H * S, 256>>>(attn, mask);

    // attn @ V -> x_heads
    av_kernel<<<dim3(S / 128, B * H), 256>>>(attn, OFF_QKV_HI + 2 * NEL * 2,
                                             OFF_QKV_LO + 2 * NEL * 2, OFF_XH);

    // split x_heads, output projection, bias
    split_kernel<<<nblk, 256>>>(nullptr, OFF_XH, OFF_XH_HI, OFF_XH_LO, nullptr, (int)NEL);
    gemm_kernel<<<ggrid, 256>>>(OFF_XH_HI, OFF_XH_LO,
                                OFF_W_HI + 3 * WEL * 2, OFF_W_LO + 3 * WEL * 2,
                                out_x, 0);
    bias_add_kernel<<<nblk, 256>>>(out_x, bo, (int)NEL);
}

// round 2
// speedup vs baseline: 1.2724x; 1.2724x over previous
#include <cuda_runtime.h>
#include <cuda_bf16.h>
#include <mma.h>

using namespace nvcuda;

// Problem constants
constexpr int B = 2, S = 2048, D = 1024, H = 16, HD = 64;
constexpr size_t NEL = (size_t)B * S * D;   // 4194304
constexpr size_t WEL = (size_t)D * D;       // 1048576

// ---------------- scratch arena ----------------
constexpr size_t OFF_IN_HI  = 0;
constexpr size_t OFF_IN_LO  = OFF_IN_HI  + 3 * NEL * 2;
constexpr size_t OFF_W_HI   = OFF_IN_LO  + 3 * NEL * 2;
constexpr size_t OFF_W_LO   = OFF_W_HI   + 4 * WEL * 2;
constexpr size_t OFF_QKV_F  = OFF_W_LO   + 4 * WEL * 2;
constexpr size_t OFF_QKV_HI = OFF_QKV_F  + 3 * NEL * 4;
constexpr size_t OFF_QKV_LO = OFF_QKV_HI + 3 * NEL * 2;
constexpr size_t OFF_XH     = OFF_QKV_LO + 3 * NEL * 2;
constexpr size_t OFF_XH_HI  = OFF_XH     + NEL * 4;
constexpr size_t OFF_XH_LO  = OFF_XH_HI  + NEL * 2;
constexpr size_t ARENA_BYTES = OFF_XH_LO + NEL * 2;

__device__ __align__(256) unsigned char g_arena[ARENA_BYTES];

#define CP_ASYNC16(dst, src) asm volatile("cp.async.cg.shared.global [%0], [%1], 16;\n" :: "r"(dst), "l"(src))
#define CP_COMMIT()  asm volatile("cp.async.commit_group;\n" ::: "memory")
#define CP_WAIT1()   asm volatile("cp.async.wait_group 1;\n" ::: "memory")

// ---------------- split fp32 -> bf16 hi/lo (optionally +bias) ----------------
__global__ void split_kernel(const float* __restrict__ src_ext, size_t src_off,
                             size_t hi_off, size_t lo_off,
                             const float* __restrict__ bias, int n)
{
    int i = blockIdx.x * blockDim.x + threadIdx.x;
    if (i >= n) return;
    const float* src = src_ext ? src_ext : (const float*)(g_arena + src_off);
    __nv_bfloat16* hi = (__nv_bfloat16*)(g_arena + hi_off);
    __nv_bfloat16* lo = (__nv_bfloat16*)(g_arena + lo_off);
    float x = src[i];
    if (bias) x += bias[i & (D - 1)];
    __nv_bfloat16 h = __float2bfloat16(x);
    hi[i] = h;
    lo[i] = __float2bfloat16(x - __bfloat162float(h));
}

// ---------------- GEMM v2: C[4096,1024] = A @ W^T, double-buffered cp.async ----
// block tile 128(m) x 64(n), K-chunk 32, 8 warps (4x2), warp tile 32x32
constexpr int G_SA = 2 * 128 * 40 * 2;           // one bf16 array, 2 stages
constexpr int G_SB = 2 * 64 * 40 * 2;
constexpr int GEMM_SMEM = 2 * G_SA + 2 * G_SB;   // 61440 bytes

__global__ __launch_bounds__(256) void gemm_kernel(
    size_t ahi_off, size_t alo_off, size_t whi_off, size_t wlo_off,
    float* __restrict__ cext, size_t c_off)
{
    const __nv_bfloat16* Ahi = (const __nv_bfloat16*)(g_arena + ahi_off);
    const __nv_bfloat16* Alo = (const __nv_bfloat16*)(g_arena + alo_off);
    const __nv_bfloat16* Whi = (const __nv_bfloat16*)(g_arena + whi_off);
    const __nv_bfloat16* Wlo = (const __nv_bfloat16*)(g_arena + wlo_off);
    float* C = cext ? cext : (float*)(g_arena + c_off);

    extern __shared__ unsigned char smraw[];
    __nv_bfloat16* Ah = (__nv_bfloat16*)(smraw);                 // [2][128][40]
    __nv_bfloat16* Al = (__nv_bfloat16*)(smraw + G_SA);
    __nv_bfloat16* Bh = (__nv_bfloat16*)(smraw + 2 * G_SA);      // [2][64][40]
    __nv_bfloat16* Bl = (__nv_bfloat16*)(smraw + 2 * G_SA + G_SB);

    int m0 = blockIdx.y * 128, n0 = blockIdx.x * 64;
    int tid = threadIdx.x, wid = tid >> 5;
    int wm = wid & 3, wn = wid >> 2;     // warp tile 32(m) x 32(n)

    auto prefetch = [&](int st, int k0) {
        // A: 128x32 per array -> 512 x 16B -> 2/thread
#pragma unroll
        for (int i = 0; i < 2; i++) {
            int v = tid + 256 * i;
            int r = v >> 2, c = (v & 3) * 8;
            size_t g = (size_t)(m0 + r) * D + k0 + c;
            CP_ASYNC16((unsigned)__cvta_generic_to_shared(Ah + (st * 128 + r) * 40 + c), Ahi + g);
            CP_ASYNC16((unsigned)__cvta_generic_to_shared(Al + (st * 128 + r) * 40 + c), Alo + g);
        }
        // B: 64x32 per array -> 256 x 16B -> 1/thread
        {
            int r = tid >> 2, c = (tid & 3) * 8;
            size_t g = (size_t)(n0 + r) * D + k0 + c;
            CP_ASYNC16((unsigned)__cvta_generic_to_shared(Bh + (st * 64 + r) * 40 + c), Whi + g);
            CP_ASYNC16((unsigned)__cvta_generic_to_shared(Bl + (st * 64 + r) * 40 + c), Wlo + g);
        }
    };

    wmma::fragment<wmma::accumulator, 16, 16, 16, float> acc[2][2];
#pragma unroll
    for (int i = 0; i < 2; i++)
#pragma unroll
        for (int j = 0; j < 2; j++) wmma::fill_fragment(acc[i][j], 0.0f);

    prefetch(0, 0);
    CP_COMMIT();
    for (int kt = 0; kt < 32; kt++) {
        if (kt < 31) prefetch((kt + 1) & 1, (kt + 1) * 32);
        CP_COMMIT();
        CP_WAIT1();
        __syncthreads();
        int st = kt & 1;
#pragma unroll
        for (int kk = 0; kk < 32; kk += 16) {
            wmma::fragment<wmma::matrix_a, 16, 16, 16, __nv_bfloat16, wmma::row_major> ah[2], al[2];
            wmma::fragment<wmma::matrix_b, 16, 16, 16, __nv_bfloat16, wmma::col_major> bh[2], bl[2];
#pragma unroll
            for (int i = 0; i < 2; i++) {
                wmma::load_matrix_sync(ah[i], Ah + (st * 128 + wm * 32 + i * 16) * 40 + kk, 40);
                wmma::load_matrix_sync(al[i], Al + (st * 128 + wm * 32 + i * 16) * 40 + kk, 40);
            }
#pragma unroll
            for (int j = 0; j < 2; j++) {
                wmma::load_matrix_sync(bh[j], Bh + (st * 64 + wn * 32 + j * 16) * 40 + kk, 40);
                wmma::load_matrix_sync(bl[j], Bl + (st * 64 + wn * 32 + j * 16) * 40 + kk, 40);
            }
#pragma unroll
            for (int i = 0; i < 2; i++)
#pragma unroll
                for (int j = 0; j < 2; j++) {
                    wmma::mma_sync(acc[i][j], ah[i], bh[j], acc[i][j]);
                    wmma::mma_sync(acc[i][j], ah[i], bl[j], acc[i][j]);
                    wmma::mma_sync(acc[i][j], al[i], bh[j], acc[i][j]);
                }
        }
        __syncthreads();
    }
#pragma unroll
    for (int i = 0; i < 2; i++)
#pragma unroll
        for (int j = 0; j < 2; j++) {
            float* p = C + (size_t)(m0 + wm * 32 + i * 16) * D + n0 + wn * 32 + j * 16;
            wmma::store_matrix_sync(p, acc[i][j], D, wmma::mem_row_major);
        }
}

// ---------------- fused attention: scores + mask + softmax + attn-write + AV ----
// block = 64 q-rows of one (b,h). Pass 1: S=QK^T/8 (staged raw into attn gmem) +
// online max/sum. Pass 2: read back, p=exp(s-m)/l, write normalized attn, O += P*V.
constexpr int A_Q   = 0;                         // Qh[64][72] bf16
constexpr int A_QL  = A_Q  + 64 * 72 * 2;        // Ql
constexpr int A_KVH = A_QL + 64 * 72 * 2;        // KVh[2][64][72]
constexpr int A_KVL = A_KVH + 2 * 64 * 72 * 2;
constexpr int A_S   = A_KVL + 2 * 64 * 72 * 2;   // Sm[64][68] f32
constexpr int A_PH  = A_S  + 64 * 68 * 4;        // Ph[64][72]
constexpr int A_PL  = A_PH + 64 * 72 * 2;
constexpr int A_M   = A_PL + 64 * 72 * 2;        // m[64] f32
constexpr int A_L   = A_M  + 64 * 4;             // l[64] f32
constexpr int ATTN_SMEM = A_L + 64 * 4;          // ~91.7 KB

__global__ __launch_bounds__(256) void attn_fused_kernel(
    size_t qhi_off, size_t qlo_off, size_t khi_off, size_t klo_off,
    size_t vhi_off, size_t vlo_off,
    const int* __restrict__ mask, float* __restrict__ attn, size_t xh_off)
{
    extern __shared__ unsigned char smraw[];
    __nv_bfloat16* Qh  = (__nv_bfloat16*)(smraw + A_Q);
    __nv_bfloat16* Ql  = (__nv_bfloat16*)(smraw + A_QL);
    __nv_bfloat16* KVh = (__nv_bfloat16*)(smraw + A_KVH);
    __nv_bfloat16* KVl = (__nv_bfloat16*)(smraw + A_KVL);
    float*         Sm  = (float*)(smraw + A_S);
    __nv_bfloat16* Ph  = (__nv_bfloat16*)(smraw + A_PH);
    __nv_bfloat16* Pl  = (__nv_bfloat16*)(smraw + A_PL);
    float*         mrow = (float*)(smraw + A_M);
    float*         lrow = (float*)(smraw + A_L);

    const __nv_bfloat16* Qhi = (const __nv_bfloat16*)(g_arena + qhi_off);
    const __nv_bfloat16* Qlo = (const __nv_bfloat16*)(g_arena + qlo_off);
    const __nv_bfloat16* Khi = (const __nv_bfloat16*)(g_arena + khi_off);
    const __nv_bfloat16* Klo = (const __nv_bfloat16*)(g_arena + klo_off);
    const __nv_bfloat16* Vhi = (const __nv_bfloat16*)(g_arena + vhi_off);
    const __nv_bfloat16* Vlo = (const __nv_bfloat16*)(g_arena + vlo_off);

    int bh = blockIdx.y;
    int b = bh >> 4, h = bh & 15;
    int q0 = blockIdx.x * 64;
    int tid = threadIdx.x, wid = tid >> 5, lane = tid & 31;
    int wm = wid & 1, wn = wid >> 1;   // mma warp tile 32(m) x 16(n) in 64x64

    auto prefetch_kv = [&](int st, const __nv_bfloat16* srch, const __nv_bfloat16* srcl, int kt) {
        size_t gbase = ((size_t)b * S + kt * 64) * D + h * HD;
#pragma unroll
        for (int i = 0; i < 2; i++) {
            int v = tid + 256 * i;
            int r = v >> 3, c = (v & 7) * 8;
            size_t g = gbase + (size_t)r * D + c;
            CP_ASYNC16((unsigned)__cvta_generic_to_shared(KVh + (st * 64 + r) * 72 + c), srch + g);
            CP_ASYNC16((unsigned)__cvta_generic_to_shared(KVl + (st * 64 + r) * 72 + c), srcl + g);
        }
    };

    // load Q tile (64x64) hi/lo
    size_t qbase = ((size_t)b * S + q0) * D + h * HD;
#pragma unroll
    for (int i = 0; i < 4; i++) {
        int v = tid + 256 * i;
        int r = v >> 4, c = (v & 15) * 4;
        *(uint2*)&Qh[r * 72 + c] = *(const uint2*)(Qhi + qbase + (size_t)r * D + c);
        *(uint2*)&Ql[r * 72 + c] = *(const uint2*)(Qlo + qbase + (size_t)r * D + c);
    }
    if (tid < 64) { mrow[tid] = -3.0e38f; lrow[tid] = 0.0f; }
    __syncthreads();

    // ---------- pass 1: scores + online softmax stats ----------
    prefetch_kv(0, Khi, Klo, 0);
    CP_COMMIT();
    for (int kt = 0; kt < 32; kt++) {
        if (kt < 31) prefetch_kv((kt + 1) & 1, Khi, Klo, kt + 1);
        CP_COMMIT();
        CP_WAIT1();
        __syncthreads();
        int st = kt & 1;

        wmma::fragment<wmma::accumulator, 16, 16, 16, float> acc[2];
        wmma::fill_fragment(acc[0], 0.0f);
        wmma::fill_fragment(acc[1], 0.0f);
#pragma unroll
        for (int kk = 0; kk < HD; kk += 16) {
            wmma::fragment<wmma::matrix_a, 16, 16, 16, __nv_bfloat16, wmma::row_major> ah[2], al[2];
            wmma::fragment<wmma::matrix_b, 16, 16, 16, __nv_bfloat16, wmma::col_major> bh_, bl_;
#pragma unroll
            for (int i = 0; i < 2; i++) {
                wmma::load_matrix_sync(ah[i], Qh + (wm * 32 + i * 16) * 72 + kk, 72);
                wmma::load_matrix_sync(al[i], Ql + (wm * 32 + i * 16) * 72 + kk, 72);
            }
            wmma::load_matrix_sync(bh_, KVh + (st * 64 + wn * 16) * 72 + kk, 72);
            wmma::load_matrix_sync(bl_, KVl + (st * 64 + wn * 16) * 72 + kk, 72);
#pragma unroll
            for (int i = 0; i < 2; i++) {
                wmma::mma_sync(acc[i], ah[i], bh_, acc[i]);
                wmma::mma_sync(acc[i], ah[i], bl_, acc[i]);
                wmma::mma_sync(acc[i], al[i], bh_, acc[i]);
            }
        }
#pragma unroll
        for (int i = 0; i < 2; i++) {
            for (int t = 0; t < acc[i].num_elements; t++) acc[i].x[t] *= 0.125f;
            wmma::store_matrix_sync(Sm + (wm * 32 + i * 16) * 68 + wn * 16, acc[i], 68, wmma::mem_row_major);
        }
        __syncthreads();

        // stats + raw write; warp w owns rows 8w..8w+7
        int colb = kt * 64;
        const int* mk = mask + (size_t)b * S + colb;
        int mv0 = mk[lane], mv1 = mk[lane + 32];
#pragma unroll
        for (int r8 = 0; r8 < 8; r8++) {
            int row = wid * 8 + r8;
            float s0 = Sm[row * 68 + lane];        if (mv0 == 0) s0 = -1e9f;
            float s1 = Sm[row * 68 + lane + 32];   if (mv1 == 0) s1 = -1e9f;
            float* arow = attn + ((size_t)bh * S + q0 + row) * S + colb;
            arow[lane] = s0;
            arow[lane + 32] = s1;
            float tmax = fmaxf(s0, s1);
#pragma unroll
            for (int o = 16; o; o >>= 1) tmax = fmaxf(tmax, __shfl_xor_sync(0xffffffffu, tmax, o));
            float mo = mrow[row];
            float mn = fmaxf(mo, tmax);
            float ts = __expf(s0 - mn) + __expf(s1 - mn);
#pragma unroll
            for (int o = 16; o; o >>= 1) ts += __shfl_xor_sync(0xffffffffu, ts, o);
            if (lane == 0) {
                lrow[row] = lrow[row] * __expf(mo - mn) + ts;
                mrow[row] = mn;
            }
        }
        __syncthreads();
    }
    if (tid < 64) lrow[tid] = 1.0f / lrow[tid];
    __syncthreads();

    // ---------- pass 2: normalize + write attn + O += P*V ----------
    wmma::fragment<wmma::accumulator, 16, 16, 16, float> accO[2];
    wmma::fill_fragment(accO[0], 0.0f);
    wmma::fill_fragment(accO[1], 0.0f);

    prefetch_kv(0, Vhi, Vlo, 0);
    CP_COMMIT();
    for (int kt = 0; kt < 32; kt++) {
        if (kt < 31) prefetch_kv((kt + 1) & 1, Vhi, Vlo, kt + 1);
        CP_COMMIT();
        CP_WAIT1();
        __syncthreads();
        int st = kt & 1, colb = kt * 64;

        // read raw scores back (block-local window, mostly L2), normalize, split
#pragma unroll
        for (int r8 = 0; r8 < 8; r8++) {
            int row = wid * 8 + r8;
            float* arow = attn + ((size_t)bh * S + q0 + row) * S + colb;
            float mr = mrow[row], il = lrow[row];
            float p0 = __expf(arow[lane] - mr) * il;
            float p1 = __expf(arow[lane + 32] - mr) * il;
            arow[lane] = p0;
            arow[lane + 32] = p1;
            __nv_bfloat16 h0 = __float2bfloat16(p0);
            __nv_bfloat16 h1 = __float2bfloat16(p1);
            Ph[row * 72 + lane] = h0;
            Ph[row * 72 + lane + 32] = h1;
            Pl[row * 72 + lane] = __float2bfloat16(p0 - __bfloat162float(h0));
            Pl[row * 72 + lane + 32] = __float2bfloat16(p1 - __bfloat162float(h1));
        }
        __syncthreads();

#pragma unroll
        for (int kk = 0; kk < 64; kk += 16) {
            wmma::fragment<wmma::matrix_a, 16, 16, 16, __nv_bfloat16, wmma::row_major> ah[2], al[2];
            wmma::fragment<wmma::matrix_b, 16, 16, 16, __nv_bfloat16, wmma::row_major> bh_, bl_;
#pragma unroll
            for (int i = 0; i < 2; i++) {
                wmma::load_matrix_sync(ah[i], Ph + (wm * 32 + i * 16) * 72 + kk, 72);
                wmma::load_matrix_sync(al[i], Pl + (wm * 32 + i * 16) * 72 + kk, 72);
            }
            wmma::load_matrix_sync(bh_, KVh + (st * 64 + kk) * 72 + wn * 16, 72);
            wmma::load_matrix_sync(bl_, KVl + (st * 64 + kk) * 72 + wn * 16, 72);
#pragma unroll
            for (int i = 0; i < 2; i++) {
                wmma::mma_sync(accO[i], ah[i], bh_, accO[i]);
                wmma::mma_sync(accO[i], ah[i], bl_, accO[i]);
                wmma::mma_sync(accO[i], al[i], bh_, accO[i]);
            }
        }
        __syncthreads();
    }

    float* XH = (float*)(g_arena + xh_off);
#pragma unroll
    for (int i = 0; i < 2; i++) {
        float* p = XH + ((size_t)b * S + q0 + wm * 32 + i * 16) * D + h * HD + wn * 16;
        wmma::store_matrix_sync(p, accO[i], D, wmma::mem_row_major);
    }
}

// ---------------- bias add on final output ----------------
__global__ void bias_add_kernel(float* __restrict__ out, const float* __restrict__ bias, int n)
{
    int i = blockIdx.x * blockDim.x + threadIdx.x;
    if (i < n) out[i] += bias[i & (D - 1)];
}

// ---------------- launch ----------------
extern "C" void kernel_launch(void* const* d_in, const int* in_sizes, int n_in,
                              void* d_out, int out_size)
{
    const float* query = (const float*)d_in[0];
    const float* key   = (const float*)d_in[1];
    const float* value = (const float*)d_in[2];
    const int*   mask  = (const int*)d_in[3];
    const float* Wq    = (const float*)d_in[4];
    const float* bq    = (const float*)d_in[5];
    const float* Wk    = (const float*)d_in[6];
    const float* bk    = (const float*)d_in[7];
    const float* Wv    = (const float*)d_in[8];
    const float* bv    = (const float*)d_in[9];
    const float* Wo    = (const float*)d_in[10];
    const float* bo    = (const float*)d_in[11];

    float* out_x = (float*)d_out;            // [B,S,D]
    float* attn  = out_x + NEL;              // [B,H,S,S]

    cudaFuncSetAttribute(gemm_kernel, cudaFuncAttributeMaxDynamicSharedMemorySize, GEMM_SMEM);
    cudaFuncSetAttribute(attn_fused_kernel, cudaFuncAttributeMaxDynamicSharedMemorySize, ATTN_SMEM);

    int nblk = (int)(NEL / 256);
    int wblk = (int)(WEL / 256);

    // split inputs + weights to bf16 hi/lo
    split_kernel<<<nblk, 256>>>(query, 0, OFF_IN_HI + 0 * NEL * 2, OFF_IN_LO + 0 * NEL * 2, nullptr, (int)NEL);
    split_kernel<<<nblk, 256>>>(key,   0, OFF_IN_HI + 1 * NEL * 2, OFF_IN_LO + 1 * NEL * 2, nullptr, (int)NEL);
    split_kernel<<<nblk, 256>>>(value, 0, OFF_IN_HI + 2 * NEL * 2, OFF_IN_LO + 2 * NEL * 2, nullptr, (int)NEL);
    split_kernel<<<wblk, 256>>>(Wq, 0, OFF_W_HI + 0 * WEL * 2, OFF_W_LO + 0 * WEL * 2, nullptr, (int)WEL);
    split_kernel<<<wblk, 256>>>(Wk, 0, OFF_W_HI + 1 * WEL * 2, OFF_W_LO + 1 * WEL * 2, nullptr, (int)WEL);
    split_kernel<<<wblk, 256>>>(Wv, 0, OFF_W_HI + 2 * WEL * 2, OFF_W_LO + 2 * WEL * 2, nullptr, (int)WEL);
    split_kernel<<<wblk, 256>>>(Wo, 0, OFF_W_HI + 3 * WEL * 2, OFF_W_LO + 3 * WEL * 2, nullptr, (int)WEL);

    // QKV projections
    dim3 ggrid(D / 64, (B * S) / 128);   // (16, 32)
    gemm_kernel<<<ggrid, 256, GEMM_SMEM>>>(OFF_IN_HI + 0 * NEL * 2, OFF_IN_LO + 0 * NEL * 2,
                                           OFF_W_HI + 0 * WEL * 2, OFF_W_LO + 0 * WEL * 2,
                                           nullptr, OFF_QKV_F + 0 * NEL * 4);
    gemm_kernel<<<ggrid, 256, GEMM_SMEM>>>(OFF_IN_HI + 1 * NEL * 2, OFF_IN_LO + 1 * NEL * 2,
                                           OFF_W_HI + 1 * WEL * 2, OFF_W_LO + 1 * WEL * 2,
                                           nullptr, OFF_QKV_F + 1 * NEL * 4);
    gemm_kernel<<<ggrid, 256, GEMM_SMEM>>>(OFF_IN_HI + 2 * NEL * 2, OFF_IN_LO + 2 * NEL * 2,
                                           OFF_W_HI + 2 * WEL * 2, OFF_W_LO + 2 * WEL * 2,
                                           nullptr, OFF_QKV_F + 2 * NEL * 4);

    // bias add + split q,k,v
    split_kernel<<<nblk, 256>>>(nullptr, OFF_QKV_F + 0 * NEL * 4,
                                OFF_QKV_HI + 0 * NEL * 2, OFF_QKV_LO + 0 * NEL * 2, bq, (int)NEL);
    split_kernel<<<nblk, 256>>>(nullptr, OFF_QKV_F + 1 * NEL * 4,
                                OFF_QKV_HI + 1 * NEL * 2, OFF_QKV_LO + 1 * NEL * 2, bk, (int)NEL);
    split_kernel<<<nblk, 256>>>(nullptr, OFF_QKV_F + 2 * NEL * 4,
                                OFF_QKV_HI + 2 * NEL * 2, OFF_QKV_LO + 2 * NEL * 2, bv, (int)NEL);

    // fused scores + softmax + attn write + AV
    attn_fused_kernel<<<dim3(S / 64, B * H), 256, ATTN_SMEM>>>(
        OFF_QKV_HI + 0 * NEL * 2, OFF_QKV_LO + 0 * NEL * 2,
        OFF_QKV_HI + 1 * NEL * 2, OFF_QKV_LO + 1 * NEL * 2,
        OFF_QKV_HI + 2 * NEL * 2, OFF_QKV_LO + 2 * NEL * 2,
        mask, attn, OFF_XH);

    // output projection
    split_kernel<<<nblk, 256>>>(nullptr, OFF_XH, OFF_XH_HI, OFF_XH_LO, nullptr, (int)NEL);
    gemm_kernel<<<ggrid, 256, GEMM_SMEM>>>(OFF_XH_HI, OFF_XH_LO,
                                           OFF_W_HI + 3 * WEL * 2, OFF_W_LO + 3 * WEL * 2,
                                           out_x, 0);
    bias_add_kernel<<<nblk, 256>>>(out_x, bo, (int)NEL);
}

// round 4
// speedup vs baseline: 1.5446x; 1.2139x over previous
#include <cuda_runtime.h>
#include <cuda_bf16.h>
#include <mma.h>
#include <cstdint>

using namespace nvcuda;

// Problem constants
constexpr int B = 2, S = 2048, D = 1024, H = 16, HD = 64;
constexpr size_t NEL = (size_t)B * S * D;   // 4194304
constexpr size_t WEL = (size_t)D * D;       // 1048576

// ---------------- scratch arena ----------------
constexpr size_t OFF_IN_HI  = 0;
constexpr size_t OFF_IN_LO  = OFF_IN_HI  + 3 * NEL * 2;
constexpr size_t OFF_W_HI   = OFF_IN_LO  + 3 * NEL * 2;
constexpr size_t OFF_W_LO   = OFF_W_HI   + 4 * WEL * 2;
constexpr size_t OFF_QKV_HI = OFF_W_LO   + 4 * WEL * 2;
constexpr size_t OFF_QKV_LO = OFF_QKV_HI + 3 * NEL * 2;
constexpr size_t OFF_XH_HI  = OFF_QKV_LO + 3 * NEL * 2;
constexpr size_t OFF_XH_LO  = OFF_XH_HI  + NEL * 2;
constexpr size_t ARENA_BYTES = OFF_XH_LO + NEL * 2;

__device__ __align__(256) unsigned char g_arena[ARENA_BYTES];

#define CP_ASYNC16(dst, src) asm volatile("cp.async.cg.shared.global [%0], [%1], 16;\n" :: "r"(dst), "l"(src))
#define CP_COMMIT()  asm volatile("cp.async.commit_group;\n" ::: "memory")
#define CP_WAIT1()   asm volatile("cp.async.wait_group 1;\n" ::: "memory")
#define CP_WAIT2()   asm volatile("cp.async.wait_group 2;\n" ::: "memory")

// ---------------- split fp32 -> bf16 hi/lo ----------------
__global__ void split_kernel(const float* __restrict__ src,
                             size_t hi_off, size_t lo_off, int n)
{
    int i = blockIdx.x * blockDim.x + threadIdx.x;
    if (i >= n) return;
    __nv_bfloat16* hi = (__nv_bfloat16*)(g_arena + hi_off);
    __nv_bfloat16* lo = (__nv_bfloat16*)(g_arena + lo_off);
    float x = src[i];
    __nv_bfloat16 h = __float2bfloat16(x);
    hi[i] = h;
    lo[i] = __float2bfloat16(x - __bfloat162float(h));
}

// ---------------- GEMM v3: C[4096,1024] = A @ W^T (+bias), fused epilogue ----
// block tile 128(m) x 64(n), K-chunk 32, 3-stage cp.async, 8 warps (32x32 tiles)
constexpr int G_SA  = 128 * 40 * 2;              // 10240 B per bf16 array
constexpr int G_SB  = 64 * 40 * 2;               // 5120
constexpr int G_STG = 2 * G_SA + 2 * G_SB;       // 30720 per stage
constexpr int GEMM_SMEM = 3 * G_STG;             // 92160

__global__ __launch_bounds__(256) void gemm_kernel(
    size_t ahi_off, size_t alo_off, size_t whi_off, size_t wlo_off,
    const float* __restrict__ bias,
    float* __restrict__ cext, size_t hi_off, size_t lo_off)
{
    const __nv_bfloat16* Ahi = (const __nv_bfloat16*)(g_arena + ahi_off);
    const __nv_bfloat16* Alo = (const __nv_bfloat16*)(g_arena + alo_off);
    const __nv_bfloat16* Whi = (const __nv_bfloat16*)(g_arena + whi_off);
    const __nv_bfloat16* Wlo = (const __nv_bfloat16*)(g_arena + wlo_off);

    extern __shared__ unsigned char smraw[];

    int m0 = blockIdx.y * 128, n0 = blockIdx.x * 64;
    int tid = threadIdx.x, wid = tid >> 5;
    int wm = wid & 3, wn = wid >> 2;     // warp tile 32(m) x 32(n)

    auto fill = [&](int st, int kt) {
        int k0 = kt * 32;
        __nv_bfloat16* Ah = (__nv_bfloat16*)(smraw + st * G_STG);
        __nv_bfloat16* Al = (__nv_bfloat16*)(smraw + st * G_STG + G_SA);
        __nv_bfloat16* Bh = (__nv_bfloat16*)(smraw + st * G_STG + 2 * G_SA);
        __nv_bfloat16* Bl = (__nv_bfloat16*)(smraw + st * G_STG + 2 * G_SA + G_SB);
#pragma unroll
        for (int i = 0; i < 2; i++) {
            int v = tid + 256 * i;
            int r = v >> 2, c = (v & 3) * 8;
            size_t g = (size_t)(m0 + r) * D + k0 + c;
            CP_ASYNC16((unsigned)__cvta_generic_to_shared(Ah + r * 40 + c), Ahi + g);
            CP_ASYNC16((unsigned)__cvta_generic_to_shared(Al + r * 40 + c), Alo + g);
        }
        {
            int r = tid >> 2, c = (tid & 3) * 8;
            size_t g = (size_t)(n0 + r) * D + k0 + c;
            CP_ASYNC16((unsigned)__cvta_generic_to_shared(Bh + r * 40 + c), Whi + g);
            CP_ASYNC16((unsigned)__cvta_generic_to_shared(Bl + r * 40 + c), Wlo + g);
        }
    };

    wmma::fragment<wmma::accumulator, 16, 16, 16, float> acc[2][2];
#pragma unroll
    for (int i = 0; i < 2; i++)
#pragma unroll
        for (int j = 0; j < 2; j++) wmma::fill_fragment(acc[i][j], 0.0f);

    fill(0, 0); CP_COMMIT();
    fill(1, 1); CP_COMMIT();
    for (int kt = 0; kt < 32; kt++) {
        if (kt + 2 < 32) fill((kt + 2) % 3, kt + 2);
        CP_COMMIT();
        CP_WAIT2();
        __syncthreads();
        int st = kt % 3;
        const __nv_bfloat16* Ah = (const __nv_bfloat16*)(smraw + st * G_STG);
        const __nv_bfloat16* Al = (const __nv_bfloat16*)(smraw + st * G_STG + G_SA);
        const __nv_bfloat16* Bh = (const __nv_bfloat16*)(smraw + st * G_STG + 2 * G_SA);
        const __nv_bfloat16* Bl = (const __nv_bfloat16*)(smraw + st * G_STG + 2 * G_SA + G_SB);
#pragma unroll
        for (int kk = 0; kk < 32; kk += 16) {
            wmma::fragment<wmma::matrix_a, 16, 16, 16, __nv_bfloat16, wmma::row_major> ah[2], al[2];
            wmma::fragment<wmma::matrix_b, 16, 16, 16, __nv_bfloat16, wmma::col_major> bh[2], bl[2];
#pragma unroll
            for (int i = 0; i < 2; i++) {
                wmma::load_matrix_sync(ah[i], Ah + (wm * 32 + i * 16) * 40 + kk, 40);
                wmma::load_matrix_sync(al[i], Al + (wm * 32 + i * 16) * 40 + kk, 40);
            }
#pragma unroll
            for (int j = 0; j < 2; j++) {
                wmma::load_matrix_sync(bh[j], Bh + (wn * 32 + j * 16) * 40 + kk, 40);
                wmma::load_matrix_sync(bl[j], Bl + (wn * 32 + j * 16) * 40 + kk, 40);
            }
#pragma unroll
            for (int i = 0; i < 2; i++)
#pragma unroll
                for (int j = 0; j < 2; j++) {
                    wmma::mma_sync(acc[i][j], ah[i], bh[j], acc[i][j]);
                    wmma::mma_sync(acc[i][j], ah[i], bl[j], acc[i][j]);
                    wmma::mma_sync(acc[i][j], al[i], bh[j], acc[i][j]);
                }
        }
        __syncthreads();
    }

    // fused epilogue: stage C in smem, add bias, write fp32 OR bf16 hi/lo split
    float* Cs = (float*)smraw;   // 128 x 68 f32 = 34816 B, fits in pipeline smem
    __syncthreads();
#pragma unroll
    for (int i = 0; i < 2; i++)
#pragma unroll
        for (int j = 0; j < 2; j++)
            wmma::store_matrix_sync(Cs + (wm * 32 + i * 16) * 68 + wn * 32 + j * 16,
                                    acc[i][j], 68, wmma::mem_row_major);
    __syncthreads();

    __nv_bfloat16* hi = (__nv_bfloat16*)(g_arena + hi_off);
    __nv_bfloat16* lo = (__nv_bfloat16*)(g_arena + lo_off);
#pragma unroll
    for (int i = 0; i < 32; i++) {
        int v = tid + 256 * i;          // 0..8191
        int r = v >> 6, c = v & 63;
        float x = Cs[r * 68 + c] + bias[n0 + c];
        size_t g = (size_t)(m0 + r) * D + n0 + c;
        if (cext) {
            cext[g] = x;
        } else {
            __nv_bfloat16 h = __float2bfloat16(x);
            hi[g] = h;
            lo[g] = __float2bfloat16(x - __bfloat162float(h));
        }
    }
}

// ---------------- fused attention: scores + mask + softmax + attn-write + AV ----
constexpr int A_Q   = 0;
constexpr int A_QL  = A_Q  + 64 * 72 * 2;
constexpr int A_KVH = A_QL + 64 * 72 * 2;
constexpr int A_KVL = A_KVH + 2 * 64 * 72 * 2;
constexpr int A_S   = A_KVL + 2 * 64 * 72 * 2;   // Sm[64][68] f32
constexpr int A_PH  = A_S  + 64 * 68 * 4;
constexpr int A_PL  = A_PH + 64 * 72 * 2;
constexpr int A_M   = A_PL + 64 * 72 * 2;
constexpr int A_L   = A_M  + 64 * 4;
constexpr int ATTN_SMEM = A_L + 64 * 4;

__global__ __launch_bounds__(256) void attn_fused_kernel(
    size_t qhi_off, size_t qlo_off, size_t khi_off, size_t klo_off,
    size_t vhi_off, size_t vlo_off,
    const int* __restrict__ mask, float* __restrict__ attn,
    size_t xhhi_off, size_t xhlo_off)
{
    extern __shared__ unsigned char smraw[];
    __nv_bfloat16* Qh  = (__nv_bfloat16*)(smraw + A_Q);
    __nv_bfloat16* Ql  = (__nv_bfloat16*)(smraw + A_QL);
    __nv_bfloat16* KVh = (__nv_bfloat16*)(smraw + A_KVH);
    __nv_bfloat16* KVl = (__nv_bfloat16*)(smraw + A_KVL);
    float*         Sm  = (float*)(smraw + A_S);
    __nv_bfloat16* Ph  = (__nv_bfloat16*)(smraw + A_PH);
    __nv_bfloat16* Pl  = (__nv_bfloat16*)(smraw + A_PL);
    float*         mrow = (float*)(smraw + A_M);
    float*         lrow = (float*)(smraw + A_L);

    const __nv_bfloat16* Qhi = (const __nv_bfloat16*)(g_arena + qhi_off);
    const __nv_bfloat16* Qlo = (const __nv_bfloat16*)(g_arena + qlo_off);
    const __nv_bfloat16* Khi = (const __nv_bfloat16*)(g_arena + khi_off);
    const __nv_bfloat16* Klo = (const __nv_bfloat16*)(g_arena + klo_off);
    const __nv_bfloat16* Vhi = (const __nv_bfloat16*)(g_arena + vhi_off);
    const __nv_bfloat16* Vlo = (const __nv_bfloat16*)(g_arena + vlo_off);

    int bh = blockIdx.y;
    int b = bh >> 4, h = bh & 15;
    int q0 = blockIdx.x * 64;
    int tid = threadIdx.x, wid = tid >> 5, lane = tid & 31;
    int wm = wid & 1, wn = wid >> 1;

    auto prefetch_kv = [&](int st, const __nv_bfloat16* srch, const __nv_bfloat16* srcl, int kt) {
        size_t gbase = ((size_t)b * S + kt * 64) * D + h * HD;
#pragma unroll
        for (int i = 0; i < 2; i++) {
            int v = tid + 256 * i;
            int r = v >> 3, c = (v & 7) * 8;
            size_t g = gbase + (size_t)r * D + c;
            CP_ASYNC16((unsigned)__cvta_generic_to_shared(KVh + (st * 64 + r) * 72 + c), srch + g);
            CP_ASYNC16((unsigned)__cvta_generic_to_shared(KVl + (st * 64 + r) * 72 + c), srcl + g);
        }
    };

    size_t qbase = ((size_t)b * S + q0) * D + h * HD;
#pragma unroll
    for (int i = 0; i < 4; i++) {
        int v = tid + 256 * i;
        int r = v >> 4, c = (v & 15) * 4;
        *(uint2*)&Qh[r * 72 + c] = *(const uint2*)(Qhi + qbase + (size_t)r * D + c);
        *(uint2*)&Ql[r * 72 + c] = *(const uint2*)(Qlo + qbase + (size_t)r * D + c);
    }
    __syncthreads();

    // ---------- pass 1: scores + per-thread online softmax stats ----------
    float tm[8], tl[8];
#pragma unroll
    for (int i = 0; i < 8; i++) { tm[i] = -3.0e38f; tl[i] = 0.0f; }

    prefetch_kv(0, Khi, Klo, 0);
    CP_COMMIT();
    for (int kt = 0; kt < 32; kt++) {
        if (kt < 31) prefetch_kv((kt + 1) & 1, Khi, Klo, kt + 1);
        CP_COMMIT();
        CP_WAIT1();
        __syncthreads();
        int st = kt & 1;

        wmma::fragment<wmma::accumulator, 16, 16, 16, float> acc[2];
        wmma::fill_fragment(acc[0], 0.0f);
        wmma::fill_fragment(acc[1], 0.0f);
#pragma unroll
        for (int kk = 0; kk < HD; kk += 16) {
            wmma::fragment<wmma::matrix_a, 16, 16, 16, __nv_bfloat16, wmma::row_major> ah[2], al[2];
            wmma::fragment<wmma::matrix_b, 16, 16, 16, __nv_bfloat16, wmma::col_major> bh_, bl_;
#pragma unroll
            for (int i = 0; i < 2; i++) {
                wmma::load_matrix_sync(ah[i], Qh + (wm * 32 + i * 16) * 72 + kk, 72);
                wmma::load_matrix_sync(al[i], Ql + (wm * 32 + i * 16) * 72 + kk, 72);
            }
            wmma::load_matrix_sync(bh_, KVh + (st * 64 + wn * 16) * 72 + kk, 72);
            wmma::load_matrix_sync(bl_, KVl + (st * 64 + wn * 16) * 72 + kk, 72);
#pragma unroll
            for (int i = 0; i < 2; i++) {
                wmma::mma_sync(acc[i], ah[i], bh_, acc[i]);
                wmma::mma_sync(acc[i], ah[i], bl_, acc[i]);
                wmma::mma_sync(acc[i], al[i], bh_, acc[i]);
            }
        }
#pragma unroll
        for (int i = 0; i < 2; i++) {
            for (int t = 0; t < acc[i].num_elements; t++) acc[i].x[t] *= 0.125f;
            wmma::store_matrix_sync(Sm + (wm * 32 + i * 16) * 68 + wn * 16, acc[i], 68, wmma::mem_row_major);
        }
        __syncthreads();

        int colb = kt * 64;
        const int* mk = mask + (size_t)b * S + colb;
        int mv0 = mk[lane], mv1 = mk[lane + 32];
#pragma unroll
        for (int r8 = 0; r8 < 8; r8++) {
            int row = wid * 8 + r8;
            float s0 = Sm[row * 68 + lane];        if (mv0 == 0) s0 = -1e9f;
            float s1 = Sm[row * 68 + lane + 32];   if (mv1 == 0) s1 = -1e9f;
            float* arow = attn + ((size_t)bh * S + q0 + row) * S + colb;
            arow[lane] = s0;
            arow[lane + 32] = s1;
            float mn = fmaxf(tm[r8], fmaxf(s0, s1));
            tl[r8] = tl[r8] * __expf(tm[r8] - mn) + __expf(s0 - mn) + __expf(s1 - mn);
            tm[r8] = mn;
        }
        __syncthreads();
    }

    // merge per-thread stats across the warp (warp wid owns rows wid*8..+7)
#pragma unroll
    for (int r8 = 0; r8 < 8; r8++) {
        float m = tm[r8], l = tl[r8];
#pragma unroll
        for (int o = 16; o; o >>= 1) {
            float mo = __shfl_xor_sync(0xffffffffu, m, o);
            float lo_ = __shfl_xor_sync(0xffffffffu, l, o);
            float mn = fmaxf(m, mo);
            l = l * __expf(m - mn) + lo_ * __expf(mo - mn);
            m = mn;
        }
        if (lane == 0) { mrow[wid * 8 + r8] = m; lrow[wid * 8 + r8] = 1.0f / l; }
    }
    __syncthreads();

    // ---------- pass 2: normalize + write attn + O += P*V ----------
    wmma::fragment<wmma::accumulator, 16, 16, 16, float> accO[2];
    wmma::fill_fragment(accO[0], 0.0f);
    wmma::fill_fragment(accO[1], 0.0f);

    prefetch_kv(0, Vhi, Vlo, 0);
    CP_COMMIT();
    for (int kt = 0; kt < 32; kt++) {
        if (kt < 31) prefetch_kv((kt + 1) & 1, Vhi, Vlo, kt + 1);
        CP_COMMIT();
        CP_WAIT1();
        __syncthreads();
        int st = kt & 1, colb = kt * 64;

#pragma unroll
        for (int r8 = 0; r8 < 8; r8++) {
            int row = wid * 8 + r8;
            float* arow = attn + ((size_t)bh * S + q0 + row) * S + colb;
            float mr = mrow[row], il = lrow[row];
            float p0 = __expf(arow[lane] - mr) * il;
            float p1 = __expf(arow[lane + 32] - mr) * il;
            arow[lane] = p0;
            arow[lane + 32] = p1;
            __nv_bfloat16 h0 = __float2bfloat16(p0);
            __nv_bfloat16 h1 = __float2bfloat16(p1);
            Ph[row * 72 + lane] = h0;
            Ph[row * 72 + lane + 32] = h1;
            Pl[row * 72 + lane] = __float2bfloat16(p0 - __bfloat162float(h0));
            Pl[row * 72 + lane + 32] = __float2bfloat16(p1 - __bfloat162float(h1));
        }
        __syncthreads();

#pragma unroll
        for (int kk = 0; kk < 64; kk += 16) {
            wmma::fragment<wmma::matrix_a, 16, 16, 16, __nv_bfloat16, wmma::row_major> ah[2], al[2];
            wmma::fragment<wmma::matrix_b, 16, 16, 16, __nv_bfloat16, wmma::row_major> bh_, bl_;
#pragma unroll
            for (int i = 0; i < 2; i++) {
                wmma::load_matrix_sync(ah[i], Ph + (wm * 32 + i * 16) * 72 + kk, 72);
                wmma::load_matrix_sync(al[i], Pl + (wm * 32 + i * 16) * 72 + kk, 72);
            }
            wmma::load_matrix_sync(bh_, KVh + (st * 64 + kk) * 72 + wn * 16, 72);
            wmma::load_matrix_sync(bl_, KVl + (st * 64 + kk) * 72 + wn * 16, 72);
#pragma unroll
            for (int i = 0; i < 2; i++) {
                wmma::mma_sync(accO[i], ah[i], bh_, accO[i]);
                wmma::mma_sync(accO[i], ah[i], bl_, accO[i]);
                wmma::mma_sync(accO[i], al[i], bh_, accO[i]);
            }
        }
        __syncthreads();
    }

    // epilogue: stage O in smem, split to bf16 hi/lo
#pragma unroll
    for (int i = 0; i < 2; i++)
        wmma::store_matrix_sync(Sm + (wm * 32 + i * 16) * 68 + wn * 16, accO[i], 68, wmma::mem_row_major);
    __syncthreads();

    __nv_bfloat16* XHhi = (__nv_bfloat16*)(g_arena + xhhi_off);
    __nv_bfloat16* XHlo = (__nv_bfloat16*)(g_arena + xhlo_off);
#pragma unroll
    for (int i = 0; i < 16; i++) {
        int v = tid + 256 * i;
        int r = v >> 6, c = v & 63;
        float x = Sm[r * 68 + c];
        __nv_bfloat16 hh = __float2bfloat16(x);
        size_t g = ((size_t)b * S + q0 + r) * D + h * HD + c;
        XHhi[g] = hh;
        XHlo[g] = __float2bfloat16(x - __bfloat162float(hh));
    }
}

// ---------------- launch ----------------
extern "C" void kernel_launch(void* const* d_in, const int* in_sizes, int n_in,
                              void* d_out, int out_size)
{
    const float* query = (const float*)d_in[0];
    const float* key   = (const float*)d_in[1];
    const float* value = (const float*)d_in[2];
    const int*   mask  = (const int*)d_in[3];
    const float* Wq    = (const float*)d_in[4];
    const float* bq    = (const float*)d_in[5];
    const float* Wk    = (const float*)d_in[6];
    const float* bk    = (const float*)d_in[7];
    const float* Wv    = (const float*)d_in[8];
    const float* bv    = (const float*)d_in[9];
    const float* Wo    = (const float*)d_in[10];
    const float* bo    = (const float*)d_in[11];

    float* out_x = (float*)d_out;            // [B,S,D]
    float* attn  = out_x + NEL;              // [B,H,S,S]

    cudaFuncSetAttribute(gemm_kernel, cudaFuncAttributeMaxDynamicSharedMemorySize, GEMM_SMEM);
    cudaFuncSetAttribute(attn_fused_kernel, cudaFuncAttributeMaxDynamicSharedMemorySize, ATTN_SMEM);

    int nblk = (int)(NEL / 256);
    int wblk = (int)(WEL / 256);

    // split inputs + weights to bf16 hi/lo
    split_kernel<<<nblk, 256>>>(query, OFF_IN_HI + 0 * NEL * 2, OFF_IN_LO + 0 * NEL * 2, (int)NEL);
    split_kernel<<<nblk, 256>>>(key,   OFF_IN_HI + 1 * NEL * 2, OFF_IN_LO + 1 * NEL * 2, (int)NEL);
    split_kernel<<<nblk, 256>>>(value, OFF_IN_HI + 2 * NEL * 2, OFF_IN_LO + 2 * NEL * 2, (int)NEL);
    split_kernel<<<wblk, 256>>>(Wq, OFF_W_HI + 0 * WEL * 2, OFF_W_LO + 0 * WEL * 2, (int)WEL);
    split_kernel<<<wblk, 256>>>(Wk, OFF_W_HI + 1 * WEL * 2, OFF_W_LO + 1 * WEL * 2, (int)WEL);
    split_kernel<<<wblk, 256>>>(Wv, OFF_W_HI + 2 * WEL * 2, OFF_W_LO + 2 * WEL * 2, (int)WEL);
    split_kernel<<<wblk, 256>>>(Wo, OFF_W_HI + 3 * WEL * 2, OFF_W_LO + 3 * WEL * 2, (int)WEL);

    // QKV projections: fused epilogue (bias + hi/lo split, no fp32 roundtrip)
    dim3 ggrid(D / 64, (B * S) / 128);   // (16, 32)
    gemm_kernel<<<ggrid, 256, GEMM_SMEM>>>(OFF_IN_HI + 0 * NEL * 2, OFF_IN_LO + 0 * NEL * 2,
                                           OFF_W_HI + 0 * WEL * 2, OFF_W_LO + 0 * WEL * 2,
                                           bq, nullptr, OFF_QKV_HI + 0 * NEL * 2, OFF_QKV_LO + 0 * NEL * 2);
    gemm_kernel<<<ggrid, 256, GEMM_SMEM>>>(OFF_IN_HI + 1 * NEL * 2, OFF_IN_LO + 1 * NEL * 2,
                                           OFF_W_HI + 1 * WEL * 2, OFF_W_LO + 1 * WEL * 2,
                                           bk, nullptr, OFF_QKV_HI + 1 * NEL * 2, OFF_QKV_LO + 1 * NEL * 2);
    gemm_kernel<<<ggrid, 256, GEMM_SMEM>>>(OFF_IN_HI + 2 * NEL * 2, OFF_IN_LO + 2 * NEL * 2,
                                           OFF_W_HI + 2 * WEL * 2, OFF_W_LO + 2 * WEL * 2,
                                           bv, nullptr, OFF_QKV_HI + 2 * NEL * 2, OFF_QKV_LO + 2 * NEL * 2);

    // fused scores + softmax + attn write + AV (writes XH hi/lo directly)
    attn_fused_kernel<<<dim3(S / 64, B * H), 256, ATTN_SMEM>>>(
        OFF_QKV_HI + 0 * NEL * 2, OFF_QKV_LO + 0 * NEL * 2,
        OFF_QKV_HI + 1 * NEL * 2, OFF_QKV_LO + 1 * NEL * 2,
        OFF_QKV_HI + 2 * NEL * 2, OFF_QKV_LO + 2 * NEL * 2,
        mask, attn, OFF_XH_HI, OFF_XH_LO);

    // output projection: fused epilogue (bias + fp32 out)
    gemm_kernel<<<ggrid, 256, GEMM_SMEM>>>(OFF_XH_HI, OFF_XH_LO,
                                           OFF_W_HI + 3 * WEL * 2, OFF_W_LO + 3 * WEL * 2,
                                           bo, out_x, 0, 0);
}